// round 3
// baseline (speedup 1.0000x reference)
#include <cuda_runtime.h>
#include <cstdint>

// Problem constants (from reference)
#define N_NODES 100000
#define N_EDGES 1600000
#define IN_C    128
#define HID_C   64
#define OUT_C   32

#define SCAN_B  1024

// ---------------- scratch (device globals; no allocation, never passed as params) ----------------
__device__ int   g_is64;                          // 1 if edge_index is int64, else int32
__device__ int   g_deg[N_NODES];
__device__ int   g_cur[N_NODES];
__device__ int   g_part[N_NODES];
__device__ int   g_bsum[128];
__device__ int   g_off[N_NODES + 1];
__device__ float g_dinv[N_NODES];
__device__ int   g_csr[N_EDGES];
__device__ __align__(16) float g_g0[(size_t)N_NODES * HID_C];   // (x@W1)*dinv
__device__ __align__(16) float g_h1[(size_t)N_NODES * HID_C];   // relu(agg1 + b1)
__device__ __align__(16) float g_g1[(size_t)N_NODES * OUT_C];   // (h1@W2)*dinv

// ---------------- edge index dtype helpers ----------------
__device__ __forceinline__ int edge_at(const void* ei, size_t idx, int is64) {
    if (is64) return (int)((const long long*)ei)[idx];
    return ((const int*)ei)[idx];
}

// Detect dtype: if data is int64 (values < 2^17), every odd 32-bit word is 0.
// If int32, odd words are random node indices (P(all 128 == 0) ~ 0).
__global__ void k_detect(const unsigned int* __restrict__ w) {
    __shared__ int any_nonzero;
    if (threadIdx.x == 0) any_nonzero = 0;
    __syncthreads();
    int nz = 0;
    for (int i = threadIdx.x; i < 128; i += 32)
        if (w[2 * i + 1] != 0u) nz = 1;
    if (nz) atomicOr(&any_nonzero, 1);
    __syncthreads();
    if (threadIdx.x == 0) g_is64 = any_nonzero ? 0 : 1;
}

// ---------------- graph preprocessing ----------------
__global__ void k_init(int n) {
    int i = blockIdx.x * blockDim.x + threadIdx.x;
    if (i < n) { g_deg[i] = 1; g_cur[i] = 0; }   // deg starts at 1 (self-loop)
}

__global__ void k_hist(const void* __restrict__ ei, int E) {
    int e = blockIdx.x * blockDim.x + threadIdx.x;
    if (e < E) {
        int c = edge_at(ei, (size_t)E + e, g_is64);   // col = target
        atomicAdd(&g_deg[c], 1);
    }
}

__global__ void k_dinv(int n) {
    int i = blockIdx.x * blockDim.x + threadIdx.x;
    if (i < n) g_dinv[i] = rsqrtf((float)g_deg[i]);
}

// 2-level exclusive scan of (deg-1) -> CSR offsets
__global__ void k_scan1(int n) {
    __shared__ int s[SCAN_B];
    int i = blockIdx.x * SCAN_B + threadIdx.x;
    int v = (i < n) ? (g_deg[i] - 1) : 0;
    s[threadIdx.x] = v;
    __syncthreads();
    for (int d = 1; d < SCAN_B; d <<= 1) {
        int t = (threadIdx.x >= d) ? s[threadIdx.x - d] : 0;
        __syncthreads();
        s[threadIdx.x] += t;
        __syncthreads();
    }
    if (i < n) g_part[i] = s[threadIdx.x] - v;    // exclusive within block
    if (threadIdx.x == SCAN_B - 1) g_bsum[blockIdx.x] = s[SCAN_B - 1];
}

__global__ void k_scan2(int nb) {
    __shared__ int s[128];
    int t = threadIdx.x;
    int v = (t < nb) ? g_bsum[t] : 0;
    s[t] = v;
    __syncthreads();
    for (int d = 1; d < 128; d <<= 1) {
        int x = (t >= d) ? s[t - d] : 0;
        __syncthreads();
        s[t] += x;
        __syncthreads();
    }
    if (t < nb) g_bsum[t] = s[t] - v;             // exclusive block offsets
}

__global__ void k_scan3(int n, int E) {
    int i = blockIdx.x * SCAN_B + threadIdx.x;
    if (i < n) g_off[i] = g_part[i] + g_bsum[blockIdx.x];
    if (i == 0) g_off[n] = E;
}

__global__ void k_fill(const void* __restrict__ ei, int E) {
    int e = blockIdx.x * blockDim.x + threadIdx.x;
    if (e < E) {
        int is64 = g_is64;
        int r = edge_at(ei, (size_t)e, is64);
        int c = edge_at(ei, (size_t)E + e, is64);
        int p = atomicAdd(&g_cur[c], 1);
        g_csr[g_off[c] + p] = r;
    }
}

// ---------------- dense GEMM:  Y[n,C] = (X[n,K] @ W[K,C]) * dinv[row] ----------------
// Layer selected at compile time: K=128 reads external X, writes g_g0.
//                                 K=64  reads g_h1 (device global), writes g_g1.
// block: 256 threads, tile 128 rows x C cols; thread: 8 rows x C/16 cols
template <int K, int C>
__global__ void k_gemm_scale(const float* __restrict__ Xext, const float* __restrict__ W,
                             int n) {
    constexpr int TM = 128;
    constexpr int KK = 16;
    constexpr int CP = C / 16;                    // 4 (C=64) or 2 (C=32)
    __shared__ float Ws[K][C];
    __shared__ float Xs[KK][TM + 4];

    const float* X = (K == IN_C) ? Xext : (const float*)g_h1;
    float*       Y = (K == IN_C) ? (float*)g_g0 : (float*)g_g1;

    int tid = threadIdx.x;
    int tx = tid & 15, ty = tid >> 4;
    int row0 = blockIdx.x * TM;

    // stage W (row-major, contiguous float4s)
    for (int i = tid; i < K * C / 4; i += 256)
        ((float4*)Ws)[i] = ((const float4*)W)[i];

    float acc[8][CP];
#pragma unroll
    for (int r = 0; r < 8; r++)
#pragma unroll
        for (int c = 0; c < CP; c++) acc[r][c] = 0.f;

    for (int kk = 0; kk < K; kk += KK) {
        __syncthreads();   // W staged / prior Xs reads done
#pragma unroll
        for (int q = 0; q < 2; q++) {
            int idx4 = tid * 2 + q;               // 0..511
            int r    = idx4 >> 2;                 // 0..127
            int k4   = (idx4 & 3) * 4;            // 0,4,8,12
            int row  = row0 + r;
            float4 vv = make_float4(0.f, 0.f, 0.f, 0.f);
            if (row < n) vv = *(const float4*)&X[(size_t)row * K + kk + k4];
            Xs[k4 + 0][r] = vv.x;
            Xs[k4 + 1][r] = vv.y;
            Xs[k4 + 2][r] = vv.z;
            Xs[k4 + 3][r] = vv.w;
        }
        __syncthreads();
#pragma unroll
        for (int k = 0; k < KK; k++) {
            float4 a0 = *(const float4*)&Xs[k][ty * 8];
            float4 a1 = *(const float4*)&Xs[k][ty * 8 + 4];
            float a[8] = {a0.x, a0.y, a0.z, a0.w, a1.x, a1.y, a1.z, a1.w};
            float b[CP];
            if constexpr (CP == 4) {
                float4 bv = *(const float4*)&Ws[kk + k][tx * 4];
                b[0] = bv.x; b[1] = bv.y; b[2] = bv.z; b[3] = bv.w;
            } else {
                float2 bv = *(const float2*)&Ws[kk + k][tx * 2];
                b[0] = bv.x; b[1] = bv.y;
            }
#pragma unroll
            for (int r = 0; r < 8; r++)
#pragma unroll
                for (int c = 0; c < CP; c++) acc[r][c] = fmaf(a[r], b[c], acc[r][c]);
        }
    }

#pragma unroll
    for (int r = 0; r < 8; r++) {
        int row = row0 + ty * 8 + r;
        if (row < n) {
            float di = g_dinv[row];
            if constexpr (CP == 4) {
                float4 o = make_float4(acc[r][0] * di, acc[r][1] * di,
                                       acc[r][2] * di, acc[r][3] * di);
                *(float4*)&Y[(size_t)row * C + tx * 4] = o;
            } else {
                float2 o = make_float2(acc[r][0] * di, acc[r][1] * di);
                *(float2*)&Y[(size_t)row * C + tx * 2] = o;
            }
        }
    }
}

// ---------------- gather aggregation: out[i] = f(dinv[i]*(g[i] + sum g[src]) + b) ----------------
// one warp per node; lane covers C/32 channels.
// C=64: reads g_g0, writes g_h1 (device global), RELU.
// C=32: reads g_g1, writes external out (param), no RELU.
template <int C, bool RELU>
__global__ void k_agg(const float* __restrict__ bias, float* __restrict__ out_ext, int n) {
    int warp = (blockIdx.x * blockDim.x + threadIdx.x) >> 5;
    int lane = threadIdx.x & 31;
    if (warp >= n) return;
    constexpr int V = C / 32;                     // 2 or 1

    const float* g   = (C == HID_C) ? (const float*)g_g0 : (const float*)g_g1;
    float*       out = (C == HID_C) ? (float*)g_h1 : out_ext;

    int beg = g_off[warp], end = g_off[warp + 1];

    if constexpr (V == 2) {
        float2 acc = *(const float2*)&g[(size_t)warp * C + lane * 2];  // self-loop
        int e = beg;
        for (; e + 4 <= end; e += 4) {
            int s0 = g_csr[e], s1 = g_csr[e + 1], s2 = g_csr[e + 2], s3 = g_csr[e + 3];
            float2 m0 = *(const float2*)&g[(size_t)s0 * C + lane * 2];
            float2 m1 = *(const float2*)&g[(size_t)s1 * C + lane * 2];
            float2 m2 = *(const float2*)&g[(size_t)s2 * C + lane * 2];
            float2 m3 = *(const float2*)&g[(size_t)s3 * C + lane * 2];
            acc.x += (m0.x + m1.x) + (m2.x + m3.x);
            acc.y += (m0.y + m1.y) + (m2.y + m3.y);
        }
        for (; e < end; ++e) {
            int s = g_csr[e];
            float2 m = *(const float2*)&g[(size_t)s * C + lane * 2];
            acc.x += m.x; acc.y += m.y;
        }
        float di = g_dinv[warp];
        float2 b = *(const float2*)&bias[lane * 2];
        float ox = di * acc.x + b.x;
        float oy = di * acc.y + b.y;
        if (RELU) { ox = fmaxf(ox, 0.f); oy = fmaxf(oy, 0.f); }
        *(float2*)&out[(size_t)warp * C + lane * 2] = make_float2(ox, oy);
    } else {
        float acc = g[(size_t)warp * C + lane];   // self-loop
        int e = beg;
        for (; e + 4 <= end; e += 4) {
            int s0 = g_csr[e], s1 = g_csr[e + 1], s2 = g_csr[e + 2], s3 = g_csr[e + 3];
            float m0 = g[(size_t)s0 * C + lane];
            float m1 = g[(size_t)s1 * C + lane];
            float m2 = g[(size_t)s2 * C + lane];
            float m3 = g[(size_t)s3 * C + lane];
            acc += (m0 + m1) + (m2 + m3);
        }
        for (; e < end; ++e) acc += g[(size_t)g_csr[e] * C + lane];
        float di = g_dinv[warp];
        float o = di * acc + bias[lane];
        if (RELU) o = fmaxf(o, 0.f);
        out[(size_t)warp * C + lane] = o;
    }
}

// ---------------- launch ----------------
extern "C" void kernel_launch(void* const* d_in, const int* in_sizes, int n_in,
                              void* d_out, int out_size) {
    const float* x  = (const float*)d_in[0];
    const void*  ei = d_in[1];                    // int32 or int64, detected on device
    const float* W1 = (const float*)d_in[2];
    const float* b1 = (const float*)d_in[3];
    const float* W2 = (const float*)d_in[4];
    const float* b2 = (const float*)d_in[5];
    float* out = (float*)d_out;

    int n = in_sizes[0] / IN_C;       // 100000
    int E = in_sizes[1] / 2;          // 1600000

    int nbN = (n + 255) / 256;
    int nbE = (E + 255) / 256;
    int nbS = (n + SCAN_B - 1) / SCAN_B;

    // 0) detect edge_index dtype
    k_detect<<<1, 32>>>((const unsigned int*)ei);

    // 1) degree histogram + dinv
    k_init<<<nbN, 256>>>(n);
    k_hist<<<nbE, 256>>>(ei, E);
    k_dinv<<<nbN, 256>>>(n);

    // 2) CSR offsets (exclusive scan) + fill
    k_scan1<<<nbS, SCAN_B>>>(n);
    k_scan2<<<1, 128>>>(nbS);
    k_scan3<<<nbS, SCAN_B>>>(n, E);
    k_fill<<<nbE, 256>>>(ei, E);

    // 3) layer 1: g0 = (x@W1)*dinv ; h1 = relu(dinv*(sum g0) + b1)
    k_gemm_scale<IN_C, HID_C><<<(n + 127) / 128, 256>>>(x, W1, n);
    k_agg<HID_C, true><<<(n * 32 + 255) / 256, 256>>>(b1, nullptr, n);

    // 4) layer 2: g1 = (h1@W2)*dinv ; out = dinv*(sum g1) + b2
    k_gemm_scale<HID_C, OUT_C><<<(n + 127) / 128, 256>>>(nullptr, W2, n);
    k_agg<OUT_C, false><<<(n * 32 + 255) / 256, 256>>>(b2, out, n);
}

// round 4
// speedup vs baseline: 1.0774x; 1.0774x over previous
#include <cuda_runtime.h>
#include <cstdint>

typedef unsigned long long ull;

// Problem constants (from reference)
#define N_NODES 100000
#define N_EDGES 1600000
#define IN_C    128
#define HID_C   64
#define OUT_C   32

#define SCAN_B  1024

// ---------------- scratch (device globals; no allocation, never passed as params) ----------------
__device__ int   g_is64;                          // 1 if edge_index is int64, else int32
__device__ int   g_deg[N_NODES];
__device__ int   g_cur[N_NODES];
__device__ int   g_part[N_NODES];
__device__ int   g_bsum[128];
__device__ int   g_off[N_NODES + 1];
__device__ float g_dinv[N_NODES];
__device__ int   g_csr[N_EDGES];
__device__ __align__(16) float g_g0[(size_t)N_NODES * HID_C];   // x@W1 (unscaled)
__device__ __align__(16) float g_h1[(size_t)N_NODES * HID_C];   // relu(agg1 + b1)
__device__ __align__(16) float g_g1[(size_t)N_NODES * OUT_C];   // h1@W2 (unscaled)

// ---------------- f32x2 packed-math helpers (sm_103a) ----------------
__device__ __forceinline__ ull pk2(float v) {
    ull d;
    asm("mov.b64 %0, {%1, %1};" : "=l"(d) : "f"(v));
    return d;
}
__device__ __forceinline__ void fma2(ull& d, ull a, ull b) {
    asm("fma.rn.f32x2 %0, %1, %2, %3;" : "=l"(d) : "l"(a), "l"(b), "l"(d));
}
__device__ __forceinline__ void unpk2(float& lo, float& hi, ull d) {
    asm("mov.b64 {%0, %1}, %2;" : "=f"(lo), "=f"(hi) : "l"(d));
}

// ---------------- edge index dtype helpers ----------------
__device__ __forceinline__ int edge_at(const void* ei, size_t idx, int is64) {
    if (is64) return (int)((const long long*)ei)[idx];
    return ((const int*)ei)[idx];
}

// Detect dtype: if data is int64 (values < 2^31), every odd 32-bit word is 0.
__global__ void k_detect(const unsigned int* __restrict__ w) {
    __shared__ int any_nonzero;
    if (threadIdx.x == 0) any_nonzero = 0;
    __syncthreads();
    int nz = 0;
    for (int i = threadIdx.x; i < 128; i += 32)
        if (w[2 * i + 1] != 0u) nz = 1;
    if (nz) atomicOr(&any_nonzero, 1);
    __syncthreads();
    if (threadIdx.x == 0) g_is64 = any_nonzero ? 0 : 1;
}

// ---------------- graph preprocessing ----------------
__global__ void k_init(int n) {
    int i = blockIdx.x * blockDim.x + threadIdx.x;
    if (i < n) { g_deg[i] = 1; g_cur[i] = 0; }   // deg starts at 1 (self-loop)
}

__global__ void k_hist(const void* __restrict__ ei, int E) {
    int e = blockIdx.x * blockDim.x + threadIdx.x;
    if (e < E) {
        int c = edge_at(ei, (size_t)E + e, g_is64);   // col = target
        atomicAdd(&g_deg[c], 1);
    }
}

// exclusive scan of (deg-1) -> CSR offsets; also computes dinv
__global__ void k_scan1(int n) {
    __shared__ int s[SCAN_B];
    int i = blockIdx.x * SCAN_B + threadIdx.x;
    int deg = (i < n) ? g_deg[i] : 1;
    if (i < n) g_dinv[i] = rsqrtf((float)deg);
    int v = (i < n) ? (deg - 1) : 0;
    s[threadIdx.x] = v;
    __syncthreads();
    for (int d = 1; d < SCAN_B; d <<= 1) {
        int t = (threadIdx.x >= d) ? s[threadIdx.x - d] : 0;
        __syncthreads();
        s[threadIdx.x] += t;
        __syncthreads();
    }
    if (i < n) g_part[i] = s[threadIdx.x] - v;    // exclusive within block
    if (threadIdx.x == SCAN_B - 1) g_bsum[blockIdx.x] = s[SCAN_B - 1];
}

__global__ void k_scan2(int nb) {
    __shared__ int s[128];
    int t = threadIdx.x;
    int v = (t < nb) ? g_bsum[t] : 0;
    s[t] = v;
    __syncthreads();
    for (int d = 1; d < 128; d <<= 1) {
        int x = (t >= d) ? s[t - d] : 0;
        __syncthreads();
        s[t] += x;
        __syncthreads();
    }
    if (t < nb) g_bsum[t] = s[t] - v;             // exclusive block offsets
}

__global__ void k_scan3(int n, int E) {
    int i = blockIdx.x * SCAN_B + threadIdx.x;
    if (i < n) g_off[i] = g_part[i] + g_bsum[blockIdx.x];
    if (i == 0) g_off[n] = E;
}

__global__ void k_fill(const void* __restrict__ ei, int E) {
    int e = blockIdx.x * blockDim.x + threadIdx.x;
    if (e < E) {
        int is64 = g_is64;
        int r = edge_at(ei, (size_t)e, is64);
        int c = edge_at(ei, (size_t)E + e, is64);
        int p = atomicAdd(&g_cur[c], 1);
        g_csr[g_off[c] + p] = r;
    }
}

// ---------------- dense GEMM (f32x2):  Y[n,C] = X[n,K] @ W[K,C]  (no scaling) ----------------
// 128 threads: tx in [0,8) covers C/8 cols each, ty in [0,16) covers 8 rows each.
// Accumulators are row-paired f32x2 (a-pairs load directly as LDS.64 from k-major Xs).
template <int K, int C>
__global__ void k_gemm(const float* __restrict__ Xext, const float* __restrict__ W, int n) {
    constexpr int TM = 128;
    constexpr int KK = 16;
    constexpr int CT = C / 8;                     // cols per thread: 8 (C=64) or 4 (C=32)
    __shared__ float Ws[K][C];
    __shared__ float Xs[KK][TM + 4];

    const float* X = (K == IN_C) ? Xext : (const float*)g_h1;
    float*       Y = (K == IN_C) ? (float*)g_g0 : (float*)g_g1;

    int tid = threadIdx.x;
    int tx = tid & 7, ty = tid >> 3;
    int row0 = blockIdx.x * TM;

    // stage W (row-major, contiguous float4s)
    for (int i = tid; i < K * C / 4; i += 128)
        ((float4*)Ws)[i] = ((const float4*)W)[i];

    ull acc[4][CT];
#pragma unroll
    for (int rp = 0; rp < 4; rp++)
#pragma unroll
        for (int c = 0; c < CT; c++) acc[rp][c] = 0ull;

    for (int kk = 0; kk < K; kk += KK) {
        __syncthreads();   // W staged / prior Xs reads done
#pragma unroll
        for (int q = 0; q < 4; q++) {
            int idx4 = q * 128 + tid;             // 0..511
            int r    = idx4 >> 2;                 // 0..127
            int k4   = (idx4 & 3) * 4;            // 0,4,8,12
            int row  = row0 + r;
            float4 vv = make_float4(0.f, 0.f, 0.f, 0.f);
            if (row < n) vv = *(const float4*)&X[(size_t)row * K + kk + k4];
            Xs[k4 + 0][r] = vv.x;
            Xs[k4 + 1][r] = vv.y;
            Xs[k4 + 2][r] = vv.z;
            Xs[k4 + 3][r] = vv.w;
        }
        __syncthreads();
#pragma unroll
        for (int k = 0; k < KK; k++) {
            ull a[4];
#pragma unroll
            for (int rp = 0; rp < 4; rp++)
                a[rp] = *(const ull*)&Xs[k][ty * 8 + 2 * rp];   // rows (2rp, 2rp+1)
            ull bb[CT];
            if constexpr (CT == 8) {
                float4 w0 = *(const float4*)&Ws[kk + k][tx * 8];
                float4 w1 = *(const float4*)&Ws[kk + k][tx * 8 + 4];
                bb[0] = pk2(w0.x); bb[1] = pk2(w0.y); bb[2] = pk2(w0.z); bb[3] = pk2(w0.w);
                bb[4] = pk2(w1.x); bb[5] = pk2(w1.y); bb[6] = pk2(w1.z); bb[7] = pk2(w1.w);
            } else {
                float4 w0 = *(const float4*)&Ws[kk + k][tx * 4];
                bb[0] = pk2(w0.x); bb[1] = pk2(w0.y); bb[2] = pk2(w0.z); bb[3] = pk2(w0.w);
            }
#pragma unroll
            for (int rp = 0; rp < 4; rp++)
#pragma unroll
                for (int c = 0; c < CT; c++) fma2(acc[rp][c], a[rp], bb[c]);
        }
    }

    // epilogue: unpack row pairs, vector stores
#pragma unroll
    for (int rp = 0; rp < 4; rp++) {
        float lo[CT], hi[CT];
#pragma unroll
        for (int c = 0; c < CT; c++) unpk2(lo[c], hi[c], acc[rp][c]);
        int r0 = row0 + ty * 8 + 2 * rp;
        if (r0 < n) {
            if constexpr (CT == 8) {
                *(float4*)&Y[(size_t)r0 * C + tx * 8]     = make_float4(lo[0], lo[1], lo[2], lo[3]);
                *(float4*)&Y[(size_t)r0 * C + tx * 8 + 4] = make_float4(lo[4], lo[5], lo[6], lo[7]);
            } else {
                *(float4*)&Y[(size_t)r0 * C + tx * 4]     = make_float4(lo[0], lo[1], lo[2], lo[3]);
            }
        }
        if (r0 + 1 < n) {
            if constexpr (CT == 8) {
                *(float4*)&Y[(size_t)(r0 + 1) * C + tx * 8]     = make_float4(hi[0], hi[1], hi[2], hi[3]);
                *(float4*)&Y[(size_t)(r0 + 1) * C + tx * 8 + 4] = make_float4(hi[4], hi[5], hi[6], hi[7]);
            } else {
                *(float4*)&Y[(size_t)(r0 + 1) * C + tx * 4]     = make_float4(hi[0], hi[1], hi[2], hi[3]);
            }
        }
    }
}

// ---------------- gather aggregation ----------------
// out[i] = f( dinv[i] * ( dinv[i]*y[i] + sum_e dinv[src_e]*y[src_e] ) + b )
// one warp per node; lane covers C/32 channels.
template <int C, bool RELU>
__global__ void k_agg(const float* __restrict__ bias, float* __restrict__ out_ext, int n) {
    int warp = (blockIdx.x * blockDim.x + threadIdx.x) >> 5;
    int lane = threadIdx.x & 31;
    if (warp >= n) return;
    constexpr int V = C / 32;                     // 2 or 1

    const float* g   = (C == HID_C) ? (const float*)g_g0 : (const float*)g_g1;
    float*       out = (C == HID_C) ? (float*)g_h1 : out_ext;

    int beg = g_off[warp], end = g_off[warp + 1];
    float di = g_dinv[warp];

    if constexpr (V == 2) {
        float2 y = *(const float2*)&g[(size_t)warp * C + lane * 2];
        float2 acc = make_float2(di * y.x, di * y.y);             // self-loop
        int e = beg;
        for (; e + 4 <= end; e += 4) {
            int s0 = g_csr[e], s1 = g_csr[e + 1], s2 = g_csr[e + 2], s3 = g_csr[e + 3];
            float d0 = g_dinv[s0], d1 = g_dinv[s1], d2 = g_dinv[s2], d3 = g_dinv[s3];
            float2 m0 = *(const float2*)&g[(size_t)s0 * C + lane * 2];
            float2 m1 = *(const float2*)&g[(size_t)s1 * C + lane * 2];
            float2 m2 = *(const float2*)&g[(size_t)s2 * C + lane * 2];
            float2 m3 = *(const float2*)&g[(size_t)s3 * C + lane * 2];
            acc.x += d0 * m0.x + d1 * m1.x + d2 * m2.x + d3 * m3.x;
            acc.y += d0 * m0.y + d1 * m1.y + d2 * m2.y + d3 * m3.y;
        }
        for (; e < end; ++e) {
            int s = g_csr[e];
            float d = g_dinv[s];
            float2 m = *(const float2*)&g[(size_t)s * C + lane * 2];
            acc.x += d * m.x; acc.y += d * m.y;
        }
        float2 b = *(const float2*)&bias[lane * 2];
        float ox = di * acc.x + b.x;
        float oy = di * acc.y + b.y;
        if (RELU) { ox = fmaxf(ox, 0.f); oy = fmaxf(oy, 0.f); }
        *(float2*)&out[(size_t)warp * C + lane * 2] = make_float2(ox, oy);
    } else {
        float acc = di * g[(size_t)warp * C + lane];              // self-loop
        int e = beg;
        for (; e + 4 <= end; e += 4) {
            int s0 = g_csr[e], s1 = g_csr[e + 1], s2 = g_csr[e + 2], s3 = g_csr[e + 3];
            float d0 = g_dinv[s0], d1 = g_dinv[s1], d2 = g_dinv[s2], d3 = g_dinv[s3];
            float m0 = g[(size_t)s0 * C + lane];
            float m1 = g[(size_t)s1 * C + lane];
            float m2 = g[(size_t)s2 * C + lane];
            float m3 = g[(size_t)s3 * C + lane];
            acc += d0 * m0 + d1 * m1 + d2 * m2 + d3 * m3;
        }
        for (; e < end; ++e) {
            int s = g_csr[e];
            acc += g_dinv[s] * g[(size_t)s * C + lane];
        }
        float o = di * acc + bias[lane];
        if (RELU) o = fmaxf(o, 0.f);
        out[(size_t)warp * C + lane] = o;
    }
}

// ---------------- launch ----------------
extern "C" void kernel_launch(void* const* d_in, const int* in_sizes, int n_in,
                              void* d_out, int out_size) {
    const float* x  = (const float*)d_in[0];
    const void*  ei = d_in[1];                    // int32 or int64, detected on device
    const float* W1 = (const float*)d_in[2];
    const float* b1 = (const float*)d_in[3];
    const float* W2 = (const float*)d_in[4];
    const float* b2 = (const float*)d_in[5];
    float* out = (float*)d_out;

    int n = in_sizes[0] / IN_C;       // 100000
    int E = in_sizes[1] / 2;          // 1600000

    int nbN = (n + 255) / 256;
    int nbE = (E + 255) / 256;
    int nbS = (n + SCAN_B - 1) / SCAN_B;

    // Fork a side stream so graph preprocessing overlaps GEMM1 (independent).
    // Stream/events are created fresh per call and intentionally not destroyed
    // (destroying a capturing stream would invalidate capture); kernel_launch
    // only runs a handful of times (correctness + capture), never during replay.
    cudaStream_t sp;
    cudaStreamCreateWithFlags(&sp, cudaStreamNonBlocking);
    cudaEvent_t eFork, eJoin;
    cudaEventCreateWithFlags(&eFork, cudaEventDisableTiming);
    cudaEventCreateWithFlags(&eJoin, cudaEventDisableTiming);

    cudaEventRecord(eFork, 0);
    cudaStreamWaitEvent(sp, eFork, 0);

    // chain A (side stream): graph preprocessing
    k_detect<<<1, 32, 0, sp>>>((const unsigned int*)ei);
    k_init<<<nbN, 256, 0, sp>>>(n);
    k_hist<<<nbE, 256, 0, sp>>>(ei, E);
    k_scan1<<<nbS, SCAN_B, 0, sp>>>(n);
    k_scan2<<<1, 128, 0, sp>>>(nbS);
    k_scan3<<<nbS, SCAN_B, 0, sp>>>(n, E);
    k_fill<<<nbE, 256, 0, sp>>>(ei, E);
    cudaEventRecord(eJoin, sp);

    // chain B (main stream): GEMM1 (depends only on x, W1)
    k_gemm<IN_C, HID_C><<<(n + 127) / 128, 128>>>(x, W1, n);

    // join, then the dependent tail
    cudaStreamWaitEvent(0, eJoin, 0);
    k_agg<HID_C, true><<<(n * 32 + 255) / 256, 256>>>(b1, nullptr, n);
    k_gemm<HID_C, OUT_C><<<(n + 127) / 128, 128>>>(nullptr, W2, n);
    k_agg<OUT_C, false><<<(n * 32 + 255) / 256, 256>>>(b2, out, n);
}

// round 5
// speedup vs baseline: 1.5015x; 1.3936x over previous
#include <cuda_runtime.h>
#include <cstdint>

typedef unsigned long long ull;

// Problem constants (from reference)
#define N_NODES 100000
#define N_EDGES 1600000
#define IN_C    128
#define HID_C   64
#define OUT_C   32

#define SCAN_B  1024

// ---------------- scratch (device globals; no allocation) ----------------
__device__ int   g_is64;                          // 1 if edge_index is int64, else int32
__device__ int   g_deg[N_NODES];                  // edge-only in-degree (self-loop added later)
__device__ int   g_cur[N_NODES];
__device__ int   g_bsum[128];                     // lookback totals, -1 = not published
__device__ int   g_off[N_NODES + 1];
__device__ float g_dinv[N_NODES];
__device__ int   g_csr[N_EDGES];
__device__ __align__(16) float g_g0[(size_t)N_NODES * HID_C];   // x@W1 (unscaled)
__device__ __align__(16) float g_h1[(size_t)N_NODES * HID_C];   // relu(agg1 + b1)
__device__ __align__(16) float g_g1[(size_t)N_NODES * OUT_C];   // (h1@W2)*dinv[row]

// ---------------- f32x2 packed-math helpers (sm_103a) ----------------
__device__ __forceinline__ ull pk2(float v) {
    ull d;
    asm("mov.b64 %0, {%1, %1};" : "=l"(d) : "f"(v));
    return d;
}
__device__ __forceinline__ void fma2(ull& d, ull a, ull b) {
    asm("fma.rn.f32x2 %0, %1, %2, %3;" : "=l"(d) : "l"(a), "l"(b), "l"(d));
}
__device__ __forceinline__ void unpk2(float& lo, float& hi, ull d) {
    asm("mov.b64 {%0, %1}, %2;" : "=f"(lo), "=f"(hi) : "l"(d));
}

// ---------------- edge index dtype helpers ----------------
__device__ __forceinline__ int edge_at(const void* ei, size_t idx, int is64) {
    if (is64) return (int)((const long long*)ei)[idx];
    return ((const int*)ei)[idx];
}

// ---------------- prep: zero deg/cur, init lookback sentinels, detect dtype ----------------
__global__ void k_prep(const unsigned int* __restrict__ w, int n) {
    int i = blockIdx.x * blockDim.x + threadIdx.x;
    if (i < n) { g_deg[i] = 0; g_cur[i] = 0; }
    if (i < 128) g_bsum[i] = -1;
    if (blockIdx.x == 0) {
        __shared__ int nz;
        if (threadIdx.x == 0) nz = 0;
        __syncthreads();
        if (threadIdx.x < 128 && w[2 * threadIdx.x + 1] != 0u) atomicOr(&nz, 1);
        __syncthreads();
        if (threadIdx.x == 0) g_is64 = nz ? 0 : 1;
    }
}

__global__ void k_hist(const void* __restrict__ ei, int E) {
    int e = blockIdx.x * blockDim.x + threadIdx.x;
    if (e < E) {
        int c = edge_at(ei, (size_t)E + e, g_is64);   // col = target
        atomicAdd(&g_deg[c], 1);
    }
}

// single-pass lookback scan: g_off = exclusive scan of deg; also dinv = rsqrt(deg+1)
// grid = 98 blocks (all resident on 148 SMs -> spin is deadlock-free)
__global__ void k_scan_lb(int n, int E) {
    __shared__ int s[SCAN_B];
    __shared__ int pre;
    int t = threadIdx.x, bid = blockIdx.x;
    int i = bid * SCAN_B + t;
    int deg = (i < n) ? g_deg[i] : 0;
    if (i < n) g_dinv[i] = rsqrtf((float)(deg + 1));
    s[t] = deg;
    if (t == 0) pre = 0;
    __syncthreads();
    for (int d = 1; d < SCAN_B; d <<= 1) {
        int x = (t >= d) ? s[t - d] : 0;
        __syncthreads();
        s[t] += x;
        __syncthreads();
    }
    if (t == SCAN_B - 1) atomicExch(&g_bsum[bid], s[t]);   // publish block total
    if (t < bid) {                                          // lookback: sum predecessors
        int v;
        do { v = atomicAdd(&g_bsum[t], 0); } while (v == -1);
        atomicAdd(&pre, v);
    }
    __syncthreads();
    if (i < n) g_off[i] = pre + s[t] - deg;                 // exclusive prefix
    if (i == n - 1) g_off[n] = pre + s[t];                  // == E
}

__global__ void k_fill(const void* __restrict__ ei, int E) {
    int e = blockIdx.x * blockDim.x + threadIdx.x;
    if (e < E) {
        int is64 = g_is64;
        int r = edge_at(ei, (size_t)e, is64);
        int c = edge_at(ei, (size_t)E + e, is64);
        int p = atomicAdd(&g_cur[c], 1);
        g_csr[g_off[c] + p] = r;
    }
}

// ---------------- dense GEMM (f32x2):  Y = X @ W  (optionally * dinv[row]) ----------------
// 128 threads: tx in [0,8) covers C/8 cols, ty in [0,16) covers 8 rows (as 4 f32x2 pairs).
template <int K, int C, bool EPI_SCALE>
__global__ void k_gemm(const float* __restrict__ Xext, const float* __restrict__ W, int n) {
    constexpr int TM = 128;
    constexpr int KK = 16;
    constexpr int CT = C / 8;                     // cols per thread: 8 (C=64) or 4 (C=32)
    __shared__ float Ws[K][C];
    __shared__ float Xs[KK][TM + 4];

    const float* X = (K == IN_C) ? Xext : (const float*)g_h1;
    float*       Y = (K == IN_C) ? (float*)g_g0 : (float*)g_g1;

    int tid = threadIdx.x;
    int tx = tid & 7, ty = tid >> 3;
    int row0 = blockIdx.x * TM;

    for (int i = tid; i < K * C / 4; i += 128)
        ((float4*)Ws)[i] = ((const float4*)W)[i];

    ull acc[4][CT];
#pragma unroll
    for (int rp = 0; rp < 4; rp++)
#pragma unroll
        for (int c = 0; c < CT; c++) acc[rp][c] = 0ull;

    for (int kk = 0; kk < K; kk += KK) {
        __syncthreads();
#pragma unroll
        for (int q = 0; q < 4; q++) {
            int idx4 = q * 128 + tid;             // 0..511
            int r    = idx4 >> 2;                 // 0..127
            int k4   = (idx4 & 3) * 4;            // 0,4,8,12
            int row  = row0 + r;
            float4 vv = make_float4(0.f, 0.f, 0.f, 0.f);
            if (row < n) vv = *(const float4*)&X[(size_t)row * K + kk + k4];
            Xs[k4 + 0][r] = vv.x;
            Xs[k4 + 1][r] = vv.y;
            Xs[k4 + 2][r] = vv.z;
            Xs[k4 + 3][r] = vv.w;
        }
        __syncthreads();
#pragma unroll
        for (int k = 0; k < KK; k++) {
            ull a[4];
#pragma unroll
            for (int rp = 0; rp < 4; rp++)
                a[rp] = *(const ull*)&Xs[k][ty * 8 + 2 * rp];
            ull bb[CT];
            if constexpr (CT == 8) {
                float4 w0 = *(const float4*)&Ws[kk + k][tx * 8];
                float4 w1 = *(const float4*)&Ws[kk + k][tx * 8 + 4];
                bb[0] = pk2(w0.x); bb[1] = pk2(w0.y); bb[2] = pk2(w0.z); bb[3] = pk2(w0.w);
                bb[4] = pk2(w1.x); bb[5] = pk2(w1.y); bb[6] = pk2(w1.z); bb[7] = pk2(w1.w);
            } else {
                float4 w0 = *(const float4*)&Ws[kk + k][tx * 4];
                bb[0] = pk2(w0.x); bb[1] = pk2(w0.y); bb[2] = pk2(w0.z); bb[3] = pk2(w0.w);
            }
#pragma unroll
            for (int rp = 0; rp < 4; rp++)
#pragma unroll
                for (int c = 0; c < CT; c++) fma2(acc[rp][c], a[rp], bb[c]);
        }
    }

#pragma unroll
    for (int rp = 0; rp < 4; rp++) {
        float lo[CT], hi[CT];
#pragma unroll
        for (int c = 0; c < CT; c++) unpk2(lo[c], hi[c], acc[rp][c]);
        int r0 = row0 + ty * 8 + 2 * rp;
        if (r0 < n) {
            float s0 = EPI_SCALE ? g_dinv[r0] : 1.0f;
            if constexpr (CT == 8) {
                *(float4*)&Y[(size_t)r0 * C + tx * 8]     = make_float4(lo[0]*s0, lo[1]*s0, lo[2]*s0, lo[3]*s0);
                *(float4*)&Y[(size_t)r0 * C + tx * 8 + 4] = make_float4(lo[4]*s0, lo[5]*s0, lo[6]*s0, lo[7]*s0);
            } else {
                *(float4*)&Y[(size_t)r0 * C + tx * 4]     = make_float4(lo[0]*s0, lo[1]*s0, lo[2]*s0, lo[3]*s0);
            }
        }
        if (r0 + 1 < n) {
            float s1 = EPI_SCALE ? g_dinv[r0 + 1] : 1.0f;
            if constexpr (CT == 8) {
                *(float4*)&Y[(size_t)(r0 + 1) * C + tx * 8]     = make_float4(hi[0]*s1, hi[1]*s1, hi[2]*s1, hi[3]*s1);
                *(float4*)&Y[(size_t)(r0 + 1) * C + tx * 8 + 4] = make_float4(hi[4]*s1, hi[5]*s1, hi[6]*s1, hi[7]*s1);
            } else {
                *(float4*)&Y[(size_t)(r0 + 1) * C + tx * 4]     = make_float4(hi[0]*s1, hi[1]*s1, hi[2]*s1, hi[3]*s1);
            }
        }
    }
}

// ---------------- layer-1 aggregation (C=64, per-edge dinv, relu) ----------------
// h1[i] = relu( dinv[i] * ( dinv[i]*g0[i] + sum_e dinv[s]*g0[s] ) + b1 )
__global__ void k_agg1(const float* __restrict__ bias, int n) {
    int warp = (blockIdx.x * blockDim.x + threadIdx.x) >> 5;
    int lane = threadIdx.x & 31;
    if (warp >= n) return;
    const float* g = (const float*)g_g0;

    int beg = g_off[warp], end = g_off[warp + 1];
    float di = g_dinv[warp];

    float2 y = *(const float2*)&g[(size_t)warp * HID_C + lane * 2];
    float2 acc = make_float2(di * y.x, di * y.y);             // self-loop
    int e = beg;
    while (e < end && (e & 3)) {
        int s = g_csr[e];
        float d = g_dinv[s];
        float2 m = *(const float2*)&g[(size_t)s * HID_C + lane * 2];
        acc.x += d * m.x; acc.y += d * m.y;
        ++e;
    }
    for (; e + 4 <= end; e += 4) {
        int4 s4 = *(const int4*)&g_csr[e];
        float d0 = g_dinv[s4.x], d1 = g_dinv[s4.y], d2 = g_dinv[s4.z], d3 = g_dinv[s4.w];
        float2 m0 = *(const float2*)&g[(size_t)s4.x * HID_C + lane * 2];
        float2 m1 = *(const float2*)&g[(size_t)s4.y * HID_C + lane * 2];
        float2 m2 = *(const float2*)&g[(size_t)s4.z * HID_C + lane * 2];
        float2 m3 = *(const float2*)&g[(size_t)s4.w * HID_C + lane * 2];
        acc.x += d0 * m0.x + d1 * m1.x + d2 * m2.x + d3 * m3.x;
        acc.y += d0 * m0.y + d1 * m1.y + d2 * m2.y + d3 * m3.y;
    }
    for (; e < end; ++e) {
        int s = g_csr[e];
        float d = g_dinv[s];
        float2 m = *(const float2*)&g[(size_t)s * HID_C + lane * 2];
        acc.x += d * m.x; acc.y += d * m.y;
    }
    float2 b = *(const float2*)&bias[lane * 2];
    float ox = fmaxf(di * acc.x + b.x, 0.f);
    float oy = fmaxf(di * acc.y + b.y, 0.f);
    *(float2*)&((float*)g_h1)[(size_t)warp * HID_C + lane * 2] = make_float2(ox, oy);
}

// ---------------- layer-2 aggregation (C=32, rows pre-scaled by dinv[src]) ----------------
// out[i] = dinv[i] * ( g1[i] + sum_e g1[s] ) + b2      (g1 already dinv[row]-scaled)
__global__ void k_agg2(const float* __restrict__ bias, float* __restrict__ out, int n) {
    int warp = (blockIdx.x * blockDim.x + threadIdx.x) >> 5;
    int lane = threadIdx.x & 31;
    if (warp >= n) return;
    const float* g = (const float*)g_g1;

    int beg = g_off[warp], end = g_off[warp + 1];

    float acc = g[(size_t)warp * OUT_C + lane];               // self-loop (pre-scaled)
    int e = beg;
    while (e < end && (e & 3)) {
        acc += g[(size_t)g_csr[e] * OUT_C + lane];
        ++e;
    }
    for (; e + 4 <= end; e += 4) {
        int4 s4 = *(const int4*)&g_csr[e];
        float m0 = g[(size_t)s4.x * OUT_C + lane];
        float m1 = g[(size_t)s4.y * OUT_C + lane];
        float m2 = g[(size_t)s4.z * OUT_C + lane];
        float m3 = g[(size_t)s4.w * OUT_C + lane];
        acc += (m0 + m1) + (m2 + m3);
    }
    for (; e < end; ++e) acc += g[(size_t)g_csr[e] * OUT_C + lane];

    float o = g_dinv[warp] * acc + bias[lane];
    out[(size_t)warp * OUT_C + lane] = o;
}

// ---------------- launch ----------------
extern "C" void kernel_launch(void* const* d_in, const int* in_sizes, int n_in,
                              void* d_out, int out_size) {
    const float* x  = (const float*)d_in[0];
    const void*  ei = d_in[1];                    // int32 or int64, detected on device
    const float* W1 = (const float*)d_in[2];
    const float* b1 = (const float*)d_in[3];
    const float* W2 = (const float*)d_in[4];
    const float* b2 = (const float*)d_in[5];
    float* out = (float*)d_out;

    int n = in_sizes[0] / IN_C;       // 100000
    int E = in_sizes[1] / 2;          // 1600000

    int nbN = (n + 255) / 256;
    int nbE = (E + 255) / 256;
    int nbS = (n + SCAN_B - 1) / SCAN_B;          // 98

    cudaStream_t sp;
    cudaStreamCreateWithFlags(&sp, cudaStreamNonBlocking);
    cudaEvent_t eFork, eJoin;
    cudaEventCreateWithFlags(&eFork, cudaEventDisableTiming);
    cudaEventCreateWithFlags(&eJoin, cudaEventDisableTiming);

    cudaEventRecord(eFork, 0);
    cudaStreamWaitEvent(sp, eFork, 0);

    // submissions 1-3: preprocessing chain on side stream
    k_prep<<<nbN, 256, 0, sp>>>((const unsigned int*)ei, n);          // 1
    k_hist<<<nbE, 256, 0, sp>>>(ei, E);                               // 2
    k_scan_lb<<<nbS, SCAN_B, 0, sp>>>(n, E);                          // 3
    // submission 4: GEMM1 on main stream (independent) -> this is the ncu-profiled launch
    k_gemm<IN_C, HID_C, false><<<(n + 127) / 128, 128>>>(x, W1, n);   // 4
    // submission 5: CSR fill, then join
    k_fill<<<nbE, 256, 0, sp>>>(ei, E);                               // 5
    cudaEventRecord(eJoin, sp);
    cudaStreamWaitEvent(0, eJoin, 0);

    // dependent tail on main stream
    k_agg1<<<(n * 32 + 255) / 256, 256>>>(b1, n);                     // 6
    k_gemm<HID_C, OUT_C, true><<<(n + 127) / 128, 128>>>(nullptr, W2, n); // 7
    k_agg2<<<(n * 32 + 255) / 256, 256>>>(b2, out, n);                // 8
}